// round 15
// baseline (speedup 1.0000x reference)
#include <cuda_runtime.h>
#include <math.h>

#define NPTS 40000
#define SNBR 16
#define CDIM 96
#define GDIM 12
#define EPSF 1e-5f

// Scratch (device globals: no allocation allowed)
__device__ float g_query[NPTS * CDIM];
__device__ float g_keyf [NPTS * CDIM];
__device__ float g_val  [NPTS * CDIM];
__device__ float g_kw   [NPTS * GDIM];   // keyf @ Ww1
__device__ float g_qw   [NPTS * GDIM];   // query @ Ww1

typedef unsigned long long ull;

__device__ __forceinline__ float warp_sum32(float v) {
    v += __shfl_xor_sync(0xffffffffu, v, 16);
    v += __shfl_xor_sync(0xffffffffu, v, 8);
    v += __shfl_xor_sync(0xffffffffu, v, 4);
    v += __shfl_xor_sync(0xffffffffu, v, 2);
    v += __shfl_xor_sync(0xffffffffu, v, 1);
    return v;
}
__device__ __forceinline__ float group_sum16(float v) {
    v += __shfl_xor_sync(0xffffffffu, v, 8);
    v += __shfl_xor_sync(0xffffffffu, v, 4);
    v += __shfl_xor_sync(0xffffffffu, v, 2);
    v += __shfl_xor_sync(0xffffffffu, v, 1);
    return v;
}
__device__ __forceinline__ float d4(float4 u, float4 x, float a) {
    return fmaf(u.x, x.x, fmaf(u.y, x.y, fmaf(u.z, x.z, fmaf(u.w, x.w, a))));
}

// ---------------------------------------------------------------------------
// Kernel A: q/k/v projections (r12 batch8 float4, proven)
// ---------------------------------------------------------------------------
__device__ __forceinline__ void proj_batch8(
    const float* __restrict__ src, float* __restrict__ dst,
    const float* Wt, const float* bias, const float* gain, const float* beta,
    float* xb, int base, int lane, bool do_ln)
{
    const int c0 = lane, c1 = lane + 32, c2 = lane + 64;
    bool ok[8];
#pragma unroll
    for (int r = 0; r < 8; r++) {
        int row = base + r;
        ok[r] = row < NPTS;
        if (ok[r]) {
            xb[r * 96 + c0] = src[row * CDIM + c0];
            xb[r * 96 + c1] = src[row * CDIM + c1];
            xb[r * 96 + c2] = src[row * CDIM + c2];
        }
    }
    __syncwarp();
    const float4* xb4 = (const float4*)xb;
    const float4* W0 = (const float4*)(Wt + c0 * 100);
    const float4* W1 = (const float4*)(Wt + c1 * 100);
    const float4* W2 = (const float4*)(Wt + c2 * 100);
    float a0[8] = {0,0,0,0,0,0,0,0}, a1[8] = {0,0,0,0,0,0,0,0}, a2[8] = {0,0,0,0,0,0,0,0};
#pragma unroll 4
    for (int j4 = 0; j4 < 24; j4++) {
        float4 u0 = W0[j4], u1 = W1[j4], u2 = W2[j4];
#pragma unroll
        for (int r = 0; r < 8; r++) {
            float4 x = xb4[r * 24 + j4];
            a0[r] = d4(u0, x, a0[r]);
            a1[r] = d4(u1, x, a1[r]);
            a2[r] = d4(u2, x, a2[r]);
        }
    }
    __syncwarp();
#pragma unroll
    for (int r = 0; r < 8; r++) {
        float y0 = a0[r] + bias[c0];
        float y1 = a1[r] + bias[c1];
        float y2 = a2[r] + bias[c2];
        if (do_ln) {
            float mu = warp_sum32(y0 + y1 + y2) * (1.0f / 96.0f);
            float e0 = y0 - mu, e1 = y1 - mu, e2 = y2 - mu;
            float var = warp_sum32(e0*e0 + e1*e1 + e2*e2) * (1.0f / 96.0f);
            float rs = rsqrtf(var + EPSF);
            y0 = fmaxf(fmaf(e0 * rs, gain[c0], beta[c0]), 0.0f);
            y1 = fmaxf(fmaf(e1 * rs, gain[c1], beta[c1]), 0.0f);
            y2 = fmaxf(fmaf(e2 * rs, gain[c2], beta[c2]), 0.0f);
        }
        if (ok[r]) {
            int row = base + r;
            dst[row * CDIM + c0] = y0;
            dst[row * CDIM + c1] = y1;
            dst[row * CDIM + c2] = y2;
        }
    }
}

__global__ void __launch_bounds__(256, 3) proj_kernel(
    const float* __restrict__ q, const float* __restrict__ k, const float* __restrict__ v,
    const float* __restrict__ Wq, const float* __restrict__ bq,
    const float* __restrict__ gq, const float* __restrict__ betaq,
    const float* __restrict__ Wk, const float* __restrict__ bk,
    const float* __restrict__ gk, const float* __restrict__ betak,
    const float* __restrict__ Wv, const float* __restrict__ bv)
{
    extern __shared__ float sm[];
    float* Wt  = sm;
    float* prm = sm + 9600;
    float* xst = sm + 9888;

    int type = blockIdx.x / 148;
    int blk  = blockIdx.x % 148;
    const float *src, *W, *bias, *gain, *beta;
    float* dst;
    bool do_ln;
    if (type == 0)      { src = q; W = Wq; bias = bq; gain = gq; beta = betaq; dst = g_query; do_ln = true;  }
    else if (type == 1) { src = k; W = Wk; bias = bk; gain = gk; beta = betak; dst = g_keyf;  do_ln = true;  }
    else                { src = v; W = Wv; bias = bv; gain = bv; beta = bv;    dst = g_val;   do_ln = false; }

    int tid = threadIdx.x;
    for (int i = tid; i < 9216; i += 256) {
        int j = i / 96, c = i % 96;
        Wt[c * 100 + j] = W[i];
    }
    for (int i = tid; i < 96; i += 256) {
        prm[i]       = bias[i];
        prm[96 + i]  = do_ln ? gain[i] : 0.0f;
        prm[192 + i] = do_ln ? beta[i] : 0.0f;
    }
    __syncthreads();

    int warp = tid >> 5, lane = tid & 31;
    float* xb = xst + warp * 768;
    for (int base = (blk * 8 + warp) * 8; base < NPTS; base += 148 * 8 * 8)
        proj_batch8(src, dst, Wt, prm, prm + 96, prm + 192, xb, base, lane, do_ln);
}

// ---------------------------------------------------------------------------
// Kernel A2: K_w / Q_w (r12, unchanged)
// ---------------------------------------------------------------------------
__global__ void __launch_bounds__(256) kw_kernel(const float* __restrict__ Ww1)
{
    __shared__ float W[96 * 13];
    int tid = threadIdx.x;
    for (int i = tid; i < 1152; i += 256) {
        int c = i / 12, g = i % 12;
        W[c * 13 + g] = Ww1[i];
    }
    __syncthreads();

    int warp = tid >> 5, lane = tid & 31;
    const int c0 = lane, c1 = lane + 32, c2 = lane + 64;
    int gwid = blockIdx.x * 8 + warp;
    int nw = gridDim.x * 8;

    for (int row = gwid; row < NPTS; row += nw) {
#pragma unroll
        for (int which = 0; which < 2; which++) {
            const float* srcb = which ? g_query : g_keyf;
            float* dstb = which ? g_qw : g_kw;
            float y0 = srcb[row * CDIM + c0];
            float y1 = srcb[row * CDIM + c1];
            float y2 = srcb[row * CDIM + c2];
            float p[12];
#pragma unroll
            for (int g = 0; g < 12; g++)
                p[g] = fmaf(y0, W[c0 * 13 + g], fmaf(y1, W[c1 * 13 + g], y2 * W[c2 * 13 + g]));
#pragma unroll
            for (int g = 0; g < 12; g++) p[g] = warp_sum32(p[g]);
            float kv = p[0];
#pragma unroll
            for (int g = 1; g < 12; g++) if (lane == g) kv = p[g];
            if (lane < 12) dstb[row * GDIM + lane] = kv;
        }
    }
}

// ---------------------------------------------------------------------------
// Kernel B: channel-stationary fused attention.
// Tile = 2 points x 16 nbrs. Warp w owns channels [w*27, w*27+27) of the 108
// fused output channels (96 peb + 12 logit); lane = neighbor (0..31).
// Weights broadcast from smem (1 wf per LDS.128); h in XOR-swizzled k-major
// smem (conflict-free stores AND loads). Warp 3 does the G=12 logit LN +
// Ww2 entirely in-lane (no shuffles); einsum via 16-lane butterfly.
// smem: Wall [108][100] = 10800 (pads hold Ww2/bp2/c2/mbuf/gw/betaw/bw2)
//       h4 24*128 = 3072 | wlog 384  -> 14,256 floats = 57,024 B : 4 blocks/SM
// ---------------------------------------------------------------------------
#define SMEMB_FLOATS 14256
#define HB 10800
#define WL 13872
#define PAD(i) sm[(((i) >> 2) * 100) + 96 + ((i) & 3)]
// pad map: Ww2 0..143 | bp2 144..239 | c2 240..251 | mbuf 256..287
//          gw 288..299 | betaw 300..311 | bw2 312..323

template<int CB>
__device__ __forceinline__ void tile_tail(
    float* sm, int lane, int nL, int pL, int sL,
    float mkE, int safeE, float* __restrict__ out)
{
    const float4* sm4 = (const float4*)sm;
    const float4* h4  = (const float4*)(sm + HB);
    float acc[27];
#pragma unroll
    for (int j = 0; j < 27; j++) acc[j] = 0.0f;
#pragma unroll 3
    for (int kq = 0; kq < 24; kq++) {
        float4 hv = h4[kq * 32 + (lane ^ (kq & 7))];
#pragma unroll
        for (int j = 0; j < 27; j++) {
            float4 wv = sm4[(CB + j) * 25 + kq];
            acc[j] = d4(wv, hv, acc[j]);
        }
    }

    if (CB == 81) {
        // in-lane logits for this lane's neighbor: u_g = acc[15+g] + mk*kw - qw + c2
        float4 kwa = *(const float4*)(g_kw + safeE * GDIM);
        float4 kwb = *(const float4*)(g_kw + safeE * GDIM + 4);
        float4 kwc = *(const float4*)(g_kw + safeE * GDIM + 8);
        float4 qwa = *(const float4*)(g_qw + nL * GDIM);
        float4 qwb = *(const float4*)(g_qw + nL * GDIM + 4);
        float4 qwc = *(const float4*)(g_qw + nL * GDIM + 8);
        float kw[12] = {kwa.x,kwa.y,kwa.z,kwa.w, kwb.x,kwb.y,kwb.z,kwb.w, kwc.x,kwc.y,kwc.z,kwc.w};
        float qw[12] = {qwa.x,qwa.y,qwa.z,qwa.w, qwb.x,qwb.y,qwb.z,qwb.w, qwc.x,qwc.y,qwc.z,qwc.w};
        float u[12];
        float susum = 0.0f;
#pragma unroll
        for (int g = 0; g < 12; g++) {
            u[g] = fmaf(mkE, kw[g], acc[15 + g]) - qw[g] + PAD(240 + g);
            susum += u[g];
        }
        float mu = susum * (1.0f / 12.0f);
        float var = 0.0f;
#pragma unroll
        for (int g = 0; g < 12; g++) { float d = u[g] - mu; var = fmaf(d, d, var); }
        float rs = rsqrtf(var * (1.0f / 12.0f) + EPSF);
        float av[12];
#pragma unroll
        for (int g = 0; g < 12; g++)
            av[g] = fmaxf(fmaf((u[g] - mu) * rs, PAD(288 + g), PAD(300 + g)), 0.0f);
#pragma unroll
        for (int g2 = 0; g2 < 12; g2++) {
            float wl = PAD(312 + g2);
#pragma unroll
            for (int h = 0; h < 12; h++)
                wl = fmaf(av[h], PAD(h * 12 + g2), wl);
            sm[WL + pL * 192 + sL * 12 + g2] = wl;
        }
        __syncwarp();
        // softmax over 16 neighbors per (point, group), * mask
        if (lane < 24) {
            int p = lane / 12, g = lane - p * 12;
            float* wp = sm + WL + p * 192;
            float m = -1e30f;
#pragma unroll
            for (int s = 0; s < SNBR; s++) m = fmaxf(m, wp[s * 12 + g]);
            float e[SNBR]; float sum = 0.0f;
#pragma unroll
            for (int s = 0; s < SNBR; s++) { e[s] = expf(wp[s * 12 + g] - m); sum += e[s]; }
            float inv = 1.0f / sum;
#pragma unroll
            for (int s = 0; s < SNBR; s++)
                wp[s * 12 + g] = e[s] * inv * PAD(256 + p * 16 + s);
        }
        __syncwarp();
    }

    // prefetch this lane's val channels (in flight across the barrier)
    const int JF = (CB == 81) ? 15 : 27;
    float va[27];
#pragma unroll
    for (int j = 0; j < 27; j++)
        if (j < JF) va[j] = g_val[safeE * CDIM + CB + j];

    __syncthreads();   // wlog final; all warps proceed to einsum

#pragma unroll
    for (int j = 0; j < 27; j++) {
        if (j < JF) {
            float vp = fmaf(va[j], mkE, acc[j] + PAD(144 + CB + j));
            float w = sm[WL + pL * 192 + sL * 12 + ((CB + j) >> 3)];
            float f = group_sum16(vp * w);
            if (sL == (j & 15)) out[nL * CDIM + CB + j] = f;
        }
    }
}

__global__ void __launch_bounds__(128, 4) attn_kernel(
    const float* __restrict__ xyz, const int* __restrict__ refidx,
    const float* __restrict__ Wp1, const float* __restrict__ bp1,
    const float* __restrict__ gp,  const float* __restrict__ betap,
    const float* __restrict__ Wp2, const float* __restrict__ bp2,
    const float* __restrict__ Ww1, const float* __restrict__ bw1,
    const float* __restrict__ gw,  const float* __restrict__ betaw,
    const float* __restrict__ Ww2, const float* __restrict__ bw2,
    float* __restrict__ out)
{
    extern __shared__ float sm[];
    int tid = threadIdx.x, warp = tid >> 5, lane = tid & 31;

    // Wall rows 0..95 = Wp2^T ([ch][k], stride 100)
    for (int i = tid; i < 9216; i += 128) {
        int j = i / 96, c = i % 96;
        sm[c * 100 + j] = Wp2[i];
    }
    for (int i = tid; i < 144; i += 128) PAD(i) = Ww2[i];
    for (int i = tid; i < 96; i += 128)  PAD(144 + i) = bp2[i];
    if (tid < 12) {
        PAD(288 + tid) = gw[tid];
        PAD(300 + tid) = betaw[tid];
        PAD(312 + tid) = bw2[tid];
    }
    __syncthreads();
    // Wall rows 96..107 = M[k][g] = sum_c Wp2[k][c]*Ww1[c][g]
    for (int i = tid; i < 1152; i += 128) {
        int g = i % 12, j = i / 12;
        float s = 0.0f;
        for (int c = 0; c < 96; c++)
            s = fmaf(sm[c * 100 + j], __ldg(&Ww1[c * 12 + g]), s);
        sm[(96 + g) * 100 + j] = s;
    }
    if (tid < 12) {
        float s = bw1[tid];
        for (int c = 0; c < 96; c++)
            s = fmaf(__ldg(&bp2[c]), __ldg(&Ww1[c * 12 + tid]), s);
        PAD(240 + tid) = s;
    }
    __syncthreads();

    // phase-1 per-lane invariants
    const int c0 = lane, c1 = lane + 32, c2i = lane + 64;
    float w100 = Wp1[c0],  w110 = Wp1[96 + c0],  w120 = Wp1[192 + c0];
    float w101 = Wp1[c1],  w111 = Wp1[96 + c1],  w121 = Wp1[192 + c1];
    float w102 = Wp1[c2i], w112 = Wp1[96 + c2i], w122 = Wp1[192 + c2i];
    float bb0 = bp1[c0], bb1 = bp1[c1], bb2 = bp1[c2i];
    float gp0 = gp[c0],  gp1 = gp[c1],  gp2 = gp[c2i];
    float be0 = betap[c0], be1 = betap[c1], be2 = betap[c2i];

    const int ppt = warp >> 1, lb = (warp & 1) * 8;
    const int pL = lane >> 4, sL = lane & 15;

    for (int n0 = blockIdx.x * 2; n0 < NPTS; n0 += gridDim.x * 2) {
        __syncthreads();   // prev tile fully consumed
        int n = n0 + ppt;
        float px = xyz[n * 3], py = xyz[n * 3 + 1], pz = xyz[n * 3 + 2];

        int safe8[8]; float mk8[8];
#pragma unroll
        for (int ss = 0; ss < 8; ss++) {
            int idx = refidx[n * SNBR + lb + ss];
            mk8[ss] = (idx >= 0) ? 1.0f : 0.0f;
            safe8[ss] = (idx >= 0) ? idx : 0;
        }
        if (lane == 0) {
#pragma unroll
            for (int ss = 0; ss < 8; ss++) PAD(256 + ppt * 16 + lb + ss) = mk8[ss];
        }

        // phase 1: h rows -> XOR-swizzled k-major smem
#pragma unroll
        for (int ss = 0; ss < 8; ss++) {
            int sf = safe8[ss]; float m = mk8[ss];
            float p0 = (xyz[sf * 3]     - px) * m;
            float p1 = (xyz[sf * 3 + 1] - py) * m;
            float p2 = (xyz[sf * 3 + 2] - pz) * m;
            float t0 = fmaf(p0, w100, fmaf(p1, w110, fmaf(p2, w120, bb0)));
            float t1 = fmaf(p0, w101, fmaf(p1, w111, fmaf(p2, w121, bb1)));
            float t2 = fmaf(p0, w102, fmaf(p1, w112, fmaf(p2, w122, bb2)));
            float mu = warp_sum32(t0 + t1 + t2) * (1.0f / 96.0f);
            float e0 = t0 - mu, e1 = t1 - mu, e2 = t2 - mu;
            float var = warp_sum32(e0*e0 + e1*e1 + e2*e2) * (1.0f / 96.0f);
            float rs = rsqrtf(var + EPSF);
            float h0 = fmaxf(fmaf(e0 * rs, gp0, be0), 0.0f);
            float h1 = fmaxf(fmaf(e1 * rs, gp1, be1), 0.0f);
            float h2 = fmaxf(fmaf(e2 * rs, gp2, be2), 0.0f);
            int nbr4 = (ppt * 16 + lb + ss) * 4;
            sm[HB + (c0  >> 2) * 128 + ((nbr4) ^ (((c0  >> 2) & 7) << 2)) + (c0  & 3)] = h0;
            sm[HB + (c1  >> 2) * 128 + ((nbr4) ^ (((c1  >> 2) & 7) << 2)) + (c1  & 3)] = h1;
            sm[HB + (c2i >> 2) * 128 + ((nbr4) ^ (((c2i >> 2) & 7) << 2)) + (c2i & 3)] = h2;
        }

        // per-lane epilogue identity (lane = neighbor)
        int nL = n0 + pL;
        int idxE = refidx[nL * SNBR + sL];
        float mkE = (idxE >= 0) ? 1.0f : 0.0f;
        int safeE = (idxE >= 0) ? idxE : 0;

        __syncthreads();   // h4 + mbuf ready

        if (warp == 0)      tile_tail<0 >(sm, lane, nL, pL, sL, mkE, safeE, out);
        else if (warp == 1) tile_tail<27>(sm, lane, nL, pL, sL, mkE, safeE, out);
        else if (warp == 2) tile_tail<54>(sm, lane, nL, pL, sL, mkE, safeE, out);
        else                tile_tail<81>(sm, lane, nL, pL, sL, mkE, safeE, out);
    }
}

// ---------------------------------------------------------------------------
extern "C" void kernel_launch(void* const* d_in, const int* in_sizes, int n_in,
                              void* d_out, int out_size) {
    const float* q     = (const float*)d_in[0];
    const float* k     = (const float*)d_in[1];
    const float* v     = (const float*)d_in[2];
    const float* xyz   = (const float*)d_in[3];
    const int*   ridx  = (const int*)  d_in[4];
    const float* Wq    = (const float*)d_in[5];
    const float* bq    = (const float*)d_in[6];
    const float* gq    = (const float*)d_in[7];
    const float* betaq = (const float*)d_in[8];
    const float* Wk    = (const float*)d_in[9];
    const float* bk    = (const float*)d_in[10];
    const float* gk    = (const float*)d_in[11];
    const float* betak = (const float*)d_in[12];
    const float* Wv    = (const float*)d_in[13];
    const float* bv    = (const float*)d_in[14];
    const float* Wp1   = (const float*)d_in[15];
    const float* bp1   = (const float*)d_in[16];
    const float* gp    = (const float*)d_in[17];
    const float* betap = (const float*)d_in[18];
    const float* Wp2   = (const float*)d_in[19];
    const float* bp2   = (const float*)d_in[20];
    const float* Ww1   = (const float*)d_in[21];
    const float* bw1   = (const float*)d_in[22];
    const float* gw    = (const float*)d_in[23];
    const float* betaw = (const float*)d_in[24];
    const float* Ww2   = (const float*)d_in[25];
    const float* bw2   = (const float*)d_in[26];
    float* out = (float*)d_out;

    size_t smemA = (size_t)16032 * sizeof(float);          // 64,128 B
    size_t smemB = (size_t)SMEMB_FLOATS * sizeof(float);   // 57,024 B
    cudaFuncSetAttribute(proj_kernel, cudaFuncAttributeMaxDynamicSharedMemorySize, (int)smemA);
    cudaFuncSetAttribute(attn_kernel, cudaFuncAttributeMaxDynamicSharedMemorySize, (int)smemB);

    proj_kernel<<<444, 256, smemA>>>(q, k, v, Wq, bq, gq, betaq, Wk, bk, gk, betak, Wv, bv);
    kw_kernel<<<296, 256>>>(Ww1);
    attn_kernel<<<592, 128, smemB>>>(xyz, ridx, Wp1, bp1, gp, betap, Wp2, bp2,
                                     Ww1, bw1, gw, betaw, Ww2, bw2, out);
}

// round 17
// speedup vs baseline: 2.0839x; 2.0839x over previous
#include <cuda_runtime.h>
#include <math.h>

#define NPTS 40000
#define SNBR 16
#define CDIM 96
#define GDIM 12
#define EPSF 1e-5f

// Scratch (device globals: no allocation allowed)
__device__ float g_query[NPTS * CDIM];
__device__ float g_keyf [NPTS * CDIM];
__device__ float g_val  [NPTS * CDIM];
__device__ float g_kw   [NPTS * GDIM];   // keyf @ Ww1
__device__ float g_qw   [NPTS * GDIM];   // query @ Ww1

typedef unsigned long long ull;

__device__ __forceinline__ float warp_sum32(float v) {
    v += __shfl_xor_sync(0xffffffffu, v, 16);
    v += __shfl_xor_sync(0xffffffffu, v, 8);
    v += __shfl_xor_sync(0xffffffffu, v, 4);
    v += __shfl_xor_sync(0xffffffffu, v, 2);
    v += __shfl_xor_sync(0xffffffffu, v, 1);
    return v;
}
__device__ __forceinline__ float group_sum16(float v) {
    v += __shfl_xor_sync(0xffffffffu, v, 8);
    v += __shfl_xor_sync(0xffffffffu, v, 4);
    v += __shfl_xor_sync(0xffffffffu, v, 2);
    v += __shfl_xor_sync(0xffffffffu, v, 1);
    return v;
}
__device__ __forceinline__ float d4(float4 u, float4 x, float a) {
    return fmaf(u.x, x.x, fmaf(u.y, x.y, fmaf(u.z, x.z, fmaf(u.w, x.w, a))));
}
// f32x2 packed helpers
__device__ __forceinline__ ull pk2(float w) {
    ull r; asm("mov.b64 %0, {%1, %1};" : "=l"(r) : "f"(w)); return r;
}
__device__ __forceinline__ void fma2(ull &d, ull a, ull b) {
    asm("fma.rn.f32x2 %0, %1, %2, %0;" : "+l"(d) : "l"(a), "l"(b));
}
__device__ __forceinline__ void unpk2(float &lo, float &hi, ull v) {
    asm("mov.b64 {%0, %1}, %2;" : "=f"(lo), "=f"(hi) : "l"(v));
}

// ---------------------------------------------------------------------------
// Kernel A: q/k/v projections (r12 batch8 float4, proven)
// ---------------------------------------------------------------------------
__device__ __forceinline__ void proj_batch8(
    const float* __restrict__ src, float* __restrict__ dst,
    const float* Wt, const float* bias, const float* gain, const float* beta,
    float* xb, int base, int lane, bool do_ln)
{
    const int c0 = lane, c1 = lane + 32, c2 = lane + 64;
    bool ok[8];
#pragma unroll
    for (int r = 0; r < 8; r++) {
        int row = base + r;
        ok[r] = row < NPTS;
        if (ok[r]) {
            xb[r * 96 + c0] = src[row * CDIM + c0];
            xb[r * 96 + c1] = src[row * CDIM + c1];
            xb[r * 96 + c2] = src[row * CDIM + c2];
        }
    }
    __syncwarp();
    const float4* xb4 = (const float4*)xb;
    const float4* W0 = (const float4*)(Wt + c0 * 100);
    const float4* W1 = (const float4*)(Wt + c1 * 100);
    const float4* W2 = (const float4*)(Wt + c2 * 100);
    float a0[8] = {0,0,0,0,0,0,0,0}, a1[8] = {0,0,0,0,0,0,0,0}, a2[8] = {0,0,0,0,0,0,0,0};
#pragma unroll 4
    for (int j4 = 0; j4 < 24; j4++) {
        float4 u0 = W0[j4], u1 = W1[j4], u2 = W2[j4];
#pragma unroll
        for (int r = 0; r < 8; r++) {
            float4 x = xb4[r * 24 + j4];
            a0[r] = d4(u0, x, a0[r]);
            a1[r] = d4(u1, x, a1[r]);
            a2[r] = d4(u2, x, a2[r]);
        }
    }
    __syncwarp();
#pragma unroll
    for (int r = 0; r < 8; r++) {
        float y0 = a0[r] + bias[c0];
        float y1 = a1[r] + bias[c1];
        float y2 = a2[r] + bias[c2];
        if (do_ln) {
            float mu = warp_sum32(y0 + y1 + y2) * (1.0f / 96.0f);
            float e0 = y0 - mu, e1 = y1 - mu, e2 = y2 - mu;
            float var = warp_sum32(e0*e0 + e1*e1 + e2*e2) * (1.0f / 96.0f);
            float rs = rsqrtf(var + EPSF);
            y0 = fmaxf(fmaf(e0 * rs, gain[c0], beta[c0]), 0.0f);
            y1 = fmaxf(fmaf(e1 * rs, gain[c1], beta[c1]), 0.0f);
            y2 = fmaxf(fmaf(e2 * rs, gain[c2], beta[c2]), 0.0f);
        }
        if (ok[r]) {
            int row = base + r;
            dst[row * CDIM + c0] = y0;
            dst[row * CDIM + c1] = y1;
            dst[row * CDIM + c2] = y2;
        }
    }
}

__global__ void __launch_bounds__(256, 3) proj_kernel(
    const float* __restrict__ q, const float* __restrict__ k, const float* __restrict__ v,
    const float* __restrict__ Wq, const float* __restrict__ bq,
    const float* __restrict__ gq, const float* __restrict__ betaq,
    const float* __restrict__ Wk, const float* __restrict__ bk,
    const float* __restrict__ gk, const float* __restrict__ betak,
    const float* __restrict__ Wv, const float* __restrict__ bv)
{
    extern __shared__ float sm[];
    float* Wt  = sm;
    float* prm = sm + 9600;
    float* xst = sm + 9888;

    int type = blockIdx.x / 148;
    int blk  = blockIdx.x % 148;
    const float *src, *W, *bias, *gain, *beta;
    float* dst;
    bool do_ln;
    if (type == 0)      { src = q; W = Wq; bias = bq; gain = gq; beta = betaq; dst = g_query; do_ln = true;  }
    else if (type == 1) { src = k; W = Wk; bias = bk; gain = gk; beta = betak; dst = g_keyf;  do_ln = true;  }
    else                { src = v; W = Wv; bias = bv; gain = bv; beta = bv;    dst = g_val;   do_ln = false; }

    int tid = threadIdx.x;
    for (int i = tid; i < 9216; i += 256) {
        int j = i / 96, c = i % 96;
        Wt[c * 100 + j] = W[i];
    }
    for (int i = tid; i < 96; i += 256) {
        prm[i]       = bias[i];
        prm[96 + i]  = do_ln ? gain[i] : 0.0f;
        prm[192 + i] = do_ln ? beta[i] : 0.0f;
    }
    __syncthreads();

    int warp = tid >> 5, lane = tid & 31;
    float* xb = xst + warp * 768;
    for (int base = (blk * 8 + warp) * 8; base < NPTS; base += 148 * 8 * 8)
        proj_batch8(src, dst, Wt, prm, prm + 96, prm + 192, xb, base, lane, do_ln);
}

// ---------------------------------------------------------------------------
// Kernel A2: K_w / Q_w (r12, unchanged)
// ---------------------------------------------------------------------------
__global__ void __launch_bounds__(256) kw_kernel(const float* __restrict__ Ww1)
{
    __shared__ float W[96 * 13];
    int tid = threadIdx.x;
    for (int i = tid; i < 1152; i += 256) {
        int c = i / 12, g = i % 12;
        W[c * 13 + g] = Ww1[i];
    }
    __syncthreads();

    int warp = tid >> 5, lane = tid & 31;
    const int c0 = lane, c1 = lane + 32, c2 = lane + 64;
    int gwid = blockIdx.x * 8 + warp;
    int nw = gridDim.x * 8;

    for (int row = gwid; row < NPTS; row += nw) {
#pragma unroll
        for (int which = 0; which < 2; which++) {
            const float* srcb = which ? g_query : g_keyf;
            float* dstb = which ? g_qw : g_kw;
            float y0 = srcb[row * CDIM + c0];
            float y1 = srcb[row * CDIM + c1];
            float y2 = srcb[row * CDIM + c2];
            float p[12];
#pragma unroll
            for (int g = 0; g < 12; g++)
                p[g] = fmaf(y0, W[c0 * 13 + g], fmaf(y1, W[c1 * 13 + g], y2 * W[c2 * 13 + g]));
#pragma unroll
            for (int g = 0; g < 12; g++) p[g] = warp_sum32(p[g]);
            float kv = p[0];
#pragma unroll
            for (int g = 1; g < 12; g++) if (lane == g) kv = p[g];
            if (lane < 12) dstb[row * GDIM + lane] = kv;
        }
    }
}

// ---------------------------------------------------------------------------
// Kernel B: fused grouped vector attention (r12 structure) with
// BATCHED phase-1 reductions (16 independent SHFL chains pipelined instead
// of 16 serial dependent ones) and __expf softmax.
// smem layout identical to r12: 14,288 floats = 57,152 B -> 4 blocks/SM.
// ---------------------------------------------------------------------------
#define SMEMB_FLOATS 14288
#define SWW2(i) sm[(((i) >> 1) * 100) + 96 + ((i) & 1)]
#define SC2(g)  sm[9600 + (g) * 100 + 96]

__global__ void __launch_bounds__(128, 4) attn_kernel(
    const float* __restrict__ xyz, const int* __restrict__ refidx,
    const float* __restrict__ Wp1, const float* __restrict__ bp1,
    const float* __restrict__ gp,  const float* __restrict__ betap,
    const float* __restrict__ Wp2, const float* __restrict__ bp2,
    const float* __restrict__ Ww1, const float* __restrict__ bw1,
    const float* __restrict__ gw,  const float* __restrict__ betaw,
    const float* __restrict__ Ww2, const float* __restrict__ bw2,
    float* __restrict__ out)
{
    extern __shared__ float sm[];
    float* Wp2t  = sm;            // 9600  ([c][100], pad slots hold Ww2)
    float* Mt    = sm + 9600;     // 1200  ([g][100], pad holds c2)
    float* wlog  = sm + 10800;    // 2 points * 16 nbr * 12
    float* hbuf  = sm + 11184;    // 4 warps * 768
    float* mbuf  = sm + 14256;    // 2 points * 16 masks

    int tid = threadIdx.x;
    for (int i = tid; i < 9216; i += 128) {
        int j = i / 96, c = i % 96;
        Wp2t[c * 100 + j] = Wp2[i];
    }
    for (int i = tid; i < 144; i += 128) SWW2(i) = Ww2[i];
    __syncthreads();

    // M[j][g] = sum_c Wp2[j][c] * Ww1[c][g], stored Mt[g*100 + j]
    for (int i = tid; i < 1152; i += 128) {
        int g = i % 12, j = i / 12;
        float s = 0.0f;
        for (int c = 0; c < 96; c++)
            s = fmaf(Wp2t[c * 100 + j], __ldg(&Ww1[c * 12 + g]), s);
        Mt[g * 100 + j] = s;
    }
    // c2_g = bp2 @ Ww1[:,g] + bw1_g
    if (tid < 12) {
        float s = bw1[tid];
        for (int c = 0; c < 96; c++)
            s = fmaf(__ldg(&bp2[c]), __ldg(&Ww1[c * 12 + tid]), s);
        SC2(tid) = s;
    }
    __syncthreads();

    int warp = tid >> 5, lane = tid & 31;
    const int c0 = lane, c1 = lane + 32, c2 = lane + 64;
    float* hbA = hbuf + warp * 768;        // [96][4] ss0..3
    float* hbB = hbA + 384;                // [96][4] ss4..7
    const double2* hA2 = (const double2*)hbA;
    const double2* hB2 = (const double2*)hbB;
    const float4* W0 = (const float4*)(Wp2t + c0 * 100);
    const float4* W1 = (const float4*)(Wp2t + c1 * 100);
    const float4* W2 = (const float4*)(Wp2t + c2 * 100);

    const int gl = lane & 15;
    const bool act = gl < 12;
    const int gidx = act ? gl : 0;
    const int halfbit = lane & 16;
    const float4* WM = (const float4*)(Mt + gidx * 100);

    // per-lane invariants
    float w1_00 = Wp1[c0],      w1_10 = Wp1[96 + c0], w1_20 = Wp1[192 + c0];
    float w1_01 = Wp1[c1],      w1_11 = Wp1[96 + c1], w1_21 = Wp1[192 + c1];
    float w1_02 = Wp1[c2],      w1_12 = Wp1[96 + c2], w1_22 = Wp1[192 + c2];
    float bb0 = bp1[c0],  bb1 = bp1[c1],  bb2 = bp1[c2];
    float gp0 = gp[c0],   gp1 = gp[c1],   gp2 = gp[c2];
    float be0 = betap[c0],be1 = betap[c1],be2 = betap[c2];
    float b20 = bp2[c0],  b21 = bp2[c1],  b22 = bp2[c2];
    const int g0 = c0 >> 3, g1 = c1 >> 3, g2 = c2 >> 3;
    float gwr = gw[gidx], bewr = betaw[gidx], bw2r = bw2[gidx];
    float c2g = SC2(gidx);

    const int ppt   = warp >> 1;        // point within pair
    const int lbase = (warp & 1) * 8;   // neighbor offset
    float* wl_pt = wlog + ppt * 192;

    for (int n0 = blockIdx.x * 2; n0 < NPTS; n0 += gridDim.x * 2) {
        __syncthreads();
        int n = n0 + ppt;

        float qwv = g_qw[n * GDIM + gidx];
        float px = xyz[n * 3], py = xyz[n * 3 + 1], pz = xyz[n * 3 + 2];

        int safe[8]; float mk[8];
#pragma unroll
        for (int ss = 0; ss < 8; ss++) {
            int idx = refidx[n * SNBR + lbase + ss];
            mk[ss]  = (idx >= 0) ? 1.0f : 0.0f;
            safe[ss] = (idx >= 0) ? idx : 0;
        }
        if (lane == 0) {
#pragma unroll
            for (int ss = 0; ss < 8; ss++) mbuf[ppt * 16 + lbase + ss] = mk[ss];
        }
        // K_w gather (12 floats/neighbor) — in flight during phase 1+2
        float kwv[8];
#pragma unroll
        for (int ss = 0; ss < 8; ss++) kwv[ss] = g_kw[safe[ss] * GDIM + gidx];

        // phase 1 (batched): t-vectors for all 8 neighbors first ...
        float t0a[8], t1a[8], t2a[8], s1[8];
#pragma unroll
        for (int ss = 0; ss < 8; ss++) {
            int sf = safe[ss]; float m = mk[ss];
            float p0 = (xyz[sf * 3]     - px) * m;
            float p1 = (xyz[sf * 3 + 1] - py) * m;
            float p2 = (xyz[sf * 3 + 2] - pz) * m;
            t0a[ss] = fmaf(p0, w1_00, fmaf(p1, w1_10, fmaf(p2, w1_20, bb0)));
            t1a[ss] = fmaf(p0, w1_01, fmaf(p1, w1_11, fmaf(p2, w1_21, bb1)));
            t2a[ss] = fmaf(p0, w1_02, fmaf(p1, w1_12, fmaf(p2, w1_22, bb2)));
            s1[ss] = t0a[ss] + t1a[ss] + t2a[ss];
        }
        // ... then 8 independent mean-chains (ILP-pipelined) ...
#pragma unroll
        for (int ss = 0; ss < 8; ss++) s1[ss] = warp_sum32(s1[ss]) * (1.0f / 96.0f);
        // ... then 8 independent variance-chains ...
        float s2[8];
#pragma unroll
        for (int ss = 0; ss < 8; ss++) {
            float e0 = t0a[ss] - s1[ss], e1 = t1a[ss] - s1[ss], e2 = t2a[ss] - s1[ss];
            s2[ss] = e0 * e0 + e1 * e1 + e2 * e2;
        }
#pragma unroll
        for (int ss = 0; ss < 8; ss++) s2[ss] = warp_sum32(s2[ss]);
        // ... then h and store
#pragma unroll
        for (int ss = 0; ss < 8; ss++) {
            float mu = s1[ss];
            float rs = rsqrtf(fmaf(s2[ss], (1.0f / 96.0f), EPSF));
            float* dstp = (ss < 4 ? hbA : hbB) + (ss & 3);
            dstp[c0 * 4] = fmaxf(fmaf((t0a[ss] - mu) * rs, gp0, be0), 0.0f);
            dstp[c1 * 4] = fmaxf(fmaf((t1a[ss] - mu) * rs, gp1, be1), 0.0f);
            dstp[c2 * 4] = fmaxf(fmaf((t2a[ss] - mu) * rs, gp2, be2), 0.0f);
        }
        __syncwarp();

        // phase 2: neighbor-paired f32x2 — 3 peb rows + 1 fused h@M row
        ull ac0[4] = {0,0,0,0}, ac1[4] = {0,0,0,0}, ac2[4] = {0,0,0,0}, ac3[4] = {0,0,0,0};
#pragma unroll 4
        for (int j4 = 0; j4 < 24; j4++) {
            float4 w0 = W0[j4], w1 = W1[j4], w2 = W2[j4], wm = WM[j4];
            float w0a[4] = {w0.x, w0.y, w0.z, w0.w};
            float w1a[4] = {w1.x, w1.y, w1.z, w1.w};
            float w2a[4] = {w2.x, w2.y, w2.z, w2.w};
            float wma[4] = {wm.x, wm.y, wm.z, wm.w};
#pragma unroll
            for (int t = 0; t < 4; t++) {
                int cc = 4 * j4 + t;
                double2 pa = hA2[cc];
                double2 pb = hB2[cc];
                ull h01 = __double_as_longlong(pa.x);
                ull h23 = __double_as_longlong(pa.y);
                ull h45 = __double_as_longlong(pb.x);
                ull h67 = __double_as_longlong(pb.y);
                ull wp;
                wp = pk2(w0a[t]);
                fma2(ac0[0], h01, wp); fma2(ac0[1], h23, wp);
                fma2(ac0[2], h45, wp); fma2(ac0[3], h67, wp);
                wp = pk2(w1a[t]);
                fma2(ac1[0], h01, wp); fma2(ac1[1], h23, wp);
                fma2(ac1[2], h45, wp); fma2(ac1[3], h67, wp);
                wp = pk2(w2a[t]);
                fma2(ac2[0], h01, wp); fma2(ac2[1], h23, wp);
                fma2(ac2[2], h45, wp); fma2(ac2[3], h67, wp);
                wp = pk2(wma[t]);
                fma2(ac3[0], h01, wp); fma2(ac3[1], h23, wp);
                fma2(ac3[2], h45, wp); fma2(ac3[3], h67, wp);
            }
        }
        float a0[8], a1[8], a2[8], a3[8];
#pragma unroll
        for (int sp = 0; sp < 4; sp++) {
            unpk2(a0[2*sp], a0[2*sp+1], ac0[sp]);
            unpk2(a1[2*sp], a1[2*sp+1], ac1[sp]);
            unpk2(a2[2*sp], a2[2*sp+1], ac2[sp]);
            unpk2(a3[2*sp], a3[2*sp+1], ac3[sp]);
        }

        // v-gather burst, then vp = val*mk + peb
        float vgA[8], vgB[8], vgC[8];
#pragma unroll
        for (int ss = 0; ss < 8; ss++) {
            vgA[ss] = g_val[safe[ss] * CDIM + c0];
            vgB[ss] = g_val[safe[ss] * CDIM + c1];
            vgC[ss] = g_val[safe[ss] * CDIM + c2];
        }
        float vp0[8], vp1[8], vp2[8];
#pragma unroll
        for (int ss = 0; ss < 8; ss++) {
            float m = mk[ss];
            vp0[ss] = fmaf(vgA[ss], m, a0[ss] + b20);
            vp1[ss] = fmaf(vgB[ss], m, a1[ss] + b21);
            vp2[ss] = fmaf(vgC[ss], m, a2[ss] + b22);
        }

        // w-logits: u = mk*K_w - Q_w + h@M + c2, then LN + relu + @Ww2
#pragma unroll
        for (int pass = 0; pass < 4; pass++) {
            int sl = 2 * pass + (halfbit >> 4);
            float uacc, mkv, kwq;
            if (halfbit) { uacc = a3[2*pass+1]; mkv = mk[2*pass+1]; kwq = kwv[2*pass+1]; }
            else         { uacc = a3[2*pass];   mkv = mk[2*pass];   kwq = kwv[2*pass];   }
            uacc = act ? (fmaf(mkv, kwq, uacc) - qwv + c2g) : 0.0f;
            float mug = group_sum16(uacc) * (1.0f / 12.0f);
            float df = act ? (uacc - mug) : 0.0f;
            float varg = group_sum16(df * df) * (1.0f / 12.0f);
            float rsg = rsqrtf(varg + EPSF);
            float aval = act ? fmaxf(fmaf(df * rsg, gwr, bewr), 0.0f) : 0.0f;
            float wl = bw2r;
#pragma unroll
            for (int hh = 0; hh < 12; hh++) {
                float av = __shfl_sync(0xffffffffu, aval, halfbit | hh);
                wl = fmaf(av, SWW2(hh * 12 + gidx), wl);
            }
            if (act) wl_pt[(lbase + sl) * 12 + gl] = wl;
        }
        __syncthreads();

        // softmax over 16 neighbors per (point, group), * mask (from smem)
        if (tid < 24) {
            int p = tid / 12, g = tid % 12;
            float* wp = wlog + p * 192;
            const float* mb = mbuf + p * 16;
            float m = -1e30f;
#pragma unroll
            for (int s = 0; s < SNBR; s++) m = fmaxf(m, wp[s * 12 + g]);
            float e[SNBR]; float sumv = 0.0f;
#pragma unroll
            for (int s = 0; s < SNBR; s++) { e[s] = __expf(wp[s * 12 + g] - m); sumv += e[s]; }
            float inv = 1.0f / sumv;
#pragma unroll
            for (int s = 0; s < SNBR; s++)
                wp[s * 12 + g] = e[s] * inv * mb[s];
        }
        __syncthreads();

        // per-warp partial einsum, combine warp pairs
        float f0 = 0, f1 = 0, f2 = 0;
#pragma unroll
        for (int ss = 0; ss < 8; ss++) {
            f0 = fmaf(vp0[ss], wl_pt[(lbase + ss) * 12 + g0], f0);
            f1 = fmaf(vp1[ss], wl_pt[(lbase + ss) * 12 + g1], f1);
            f2 = fmaf(vp2[ss], wl_pt[(lbase + ss) * 12 + g2], f2);
        }
        hbA[c0] = f0; hbA[c1] = f1; hbA[c2] = f2;
        __syncthreads();

        for (int i = tid; i < 192; i += 128) {
            int p = i / 96, c = i % 96;
            out[(n0 + p) * CDIM + c] = hbuf[(p * 2) * 768 + c] + hbuf[(p * 2 + 1) * 768 + c];
        }
    }
}

// ---------------------------------------------------------------------------
extern "C" void kernel_launch(void* const* d_in, const int* in_sizes, int n_in,
                              void* d_out, int out_size) {
    const float* q     = (const float*)d_in[0];
    const float* k     = (const float*)d_in[1];
    const float* v     = (const float*)d_in[2];
    const float* xyz   = (const float*)d_in[3];
    const int*   ridx  = (const int*)  d_in[4];
    const float* Wq    = (const float*)d_in[5];
    const float* bq    = (const float*)d_in[6];
    const float* gq    = (const float*)d_in[7];
    const float* betaq = (const float*)d_in[8];
    const float* Wk    = (const float*)d_in[9];
    const float* bk    = (const float*)d_in[10];
    const float* gk    = (const float*)d_in[11];
    const float* betak = (const float*)d_in[12];
    const float* Wv    = (const float*)d_in[13];
    const float* bv    = (const float*)d_in[14];
    const float* Wp1   = (const float*)d_in[15];
    const float* bp1   = (const float*)d_in[16];
    const float* gp    = (const float*)d_in[17];
    const float* betap = (const float*)d_in[18];
    const float* Wp2   = (const float*)d_in[19];
    const float* bp2   = (const float*)d_in[20];
    const float* Ww1   = (const float*)d_in[21];
    const float* bw1   = (const float*)d_in[22];
    const float* gw    = (const float*)d_in[23];
    const float* betaw = (const float*)d_in[24];
    const float* Ww2   = (const float*)d_in[25];
    const float* bw2   = (const float*)d_in[26];
    float* out = (float*)d_out;

    size_t smemA = (size_t)16032 * sizeof(float);          // 64,128 B
    size_t smemB = (size_t)SMEMB_FLOATS * sizeof(float);   // 57,152 B
    cudaFuncSetAttribute(proj_kernel, cudaFuncAttributeMaxDynamicSharedMemorySize, (int)smemA);
    cudaFuncSetAttribute(attn_kernel, cudaFuncAttributeMaxDynamicSharedMemorySize, (int)smemB);

    proj_kernel<<<444, 256, smemA>>>(q, k, v, Wq, bq, gq, betaq, Wk, bk, gk, betak, Wv, bv);
    kw_kernel<<<296, 256>>>(Ww1);
    attn_kernel<<<592, 128, smemB>>>(xyz, ridx, Wp1, bp1, gp, betap, Wp2, bp2,
                                     Ww1, bw1, gw, betaw, Ww2, bw2, out);
}